// round 6
// baseline (speedup 1.0000x reference)
#include <cuda_runtime.h>
#include <cuda_bf16.h>
#include <math.h>

// Problem constants
#define S_   2048
#define D_   1024
#define NH_  8
#define NKV_ 2
#define HD_  128
#define WS_  64
#define E_   16
#define HDIM_ 512

// ---------------- scratch (device globals; no allocation allowed) ----------------
__device__ float g_h1[S_ * D_];            // rmsnorm1 output
__device__ float g_q[S_ * D_];             // [s][h*128+d]
__device__ float g_k[S_ * NKV_ * HD_];     // [s][kh*128+d]
__device__ float g_v[S_ * NKV_ * HD_];
__device__ float g_attn[S_ * D_];          // attention output (pre-WO)
__device__ float g_x1[S_ * D_];            // x + attn@wo + bo
__device__ float g_h2[S_ * D_];            // rmsnorm2 output
__device__ float g_hmid[E_ * S_ * HDIM_];  // per-(expert,pos) hidden (64MB)
__device__ float g_contrib[S_ * 2 * D_];   // per-(token,slot) ffn contribution
__device__ float g_gate[S_ * 2];           // gate weight per (token,slot)
__device__ int   g_list[E_ * S_];          // expert -> list of (token*2+slot)
__device__ int   g_cnt[E_];
__device__ float g_colsum[E_];

// ---------------- utility kernels ----------------
__global__ void zero_kernel() {
    int t = threadIdx.x;
    if (t < E_) { g_cnt[t] = 0; g_colsum[t] = 0.f; }
}

__device__ __forceinline__ void rms_row(const float* __restrict__ x,
                                        const float* __restrict__ w,
                                        float* __restrict__ o) {
    int n = blockIdx.x;
    int tid = threadIdx.x;            // 256 threads, 4 elems each
    float4 xv = *(const float4*)&x[n * D_ + tid * 4];
    float s = xv.x * xv.x + xv.y * xv.y + xv.z * xv.z + xv.w * xv.w;
    #pragma unroll
    for (int off = 16; off; off >>= 1) s += __shfl_xor_sync(0xffffffffu, s, off);
    __shared__ float part[8];
    __shared__ float inv;
    int wid = tid >> 5, lane = tid & 31;
    if (lane == 0) part[wid] = s;
    __syncthreads();
    if (tid == 0) {
        float t = 0.f;
        #pragma unroll
        for (int i = 0; i < 8; i++) t += part[i];
        inv = rsqrtf(t / (float)D_ + 1e-6f);
    }
    __syncthreads();
    float4 wv = *(const float4*)&w[tid * 4];
    float4 ov;
    ov.x = xv.x * inv * wv.x; ov.y = xv.y * inv * wv.y;
    ov.z = xv.z * inv * wv.z; ov.w = xv.w * inv * wv.w;
    *(float4*)&o[n * D_ + tid * 4] = ov;
}

__global__ void __launch_bounds__(256) rmsnorm1_kernel(const float* __restrict__ x,
                                                       const float* __restrict__ w) {
    rms_row(x, w, g_h1);
}

__global__ void __launch_bounds__(256) rmsnorm2_kernel(const float* __restrict__ w) {
    rms_row(g_x1, w, g_h2);
}

// ---------------- SGEMM core: 128x128 tile, BK=8, 256 threads, 8x8 micro ----------------
__device__ __forceinline__ void gemm_core(const float* __restrict__ aRowPtr, // this thread's A row base
                                          const float* __restrict__ bPtr,   // B + bn (row-major, ldb)
                                          int ldb, int Kdim,
                                          float (&acc)[8][8]) {
    __shared__ float As[8][132];
    __shared__ float Bs[8][128];
    int tid = threadIdx.x;
    int tx = tid & 15, ty = tid >> 4;
    int a_row = tid >> 1;
    int aK = (tid & 1) * 4;
    int b_row = tid >> 5;
    int b_col = (tid & 31) << 2;
    #pragma unroll
    for (int i = 0; i < 8; i++)
        #pragma unroll
        for (int j = 0; j < 8; j++) acc[i][j] = 0.f;

    for (int k0 = 0; k0 < Kdim; k0 += 8) {
        float4 av = *(const float4*)(aRowPtr + k0 + aK);
        As[aK + 0][a_row] = av.x; As[aK + 1][a_row] = av.y;
        As[aK + 2][a_row] = av.z; As[aK + 3][a_row] = av.w;
        float4 bv = *(const float4*)(bPtr + (size_t)(k0 + b_row) * ldb + b_col);
        *(float4*)&Bs[b_row][b_col] = bv;
        __syncthreads();
        #pragma unroll
        for (int k = 0; k < 8; ++k) {
            float4 a0 = *(float4*)&As[k][ty * 8];
            float4 a1 = *(float4*)&As[k][ty * 8 + 4];
            float4 b0 = *(float4*)&Bs[k][tx * 8];
            float4 b1 = *(float4*)&Bs[k][tx * 8 + 4];
            float ra[8] = {a0.x, a0.y, a0.z, a0.w, a1.x, a1.y, a1.z, a1.w};
            float rb[8] = {b0.x, b0.y, b0.z, b0.w, b1.x, b1.y, b1.z, b1.w};
            #pragma unroll
            for (int i = 0; i < 8; i++)
                #pragma unroll
                for (int j = 0; j < 8; j++) acc[i][j] += ra[i] * rb[j];
        }
        __syncthreads();
    }
}

// ---------------- fused QKV GEMM (N tiles 0-7: Q, 8-9: K, 10-11: V) ----------------
__global__ void __launch_bounds__(256) qkv_kernel(const float* __restrict__ wq, const float* __restrict__ bq,
                                                  const float* __restrict__ wk, const float* __restrict__ bk,
                                                  const float* __restrict__ wv, const float* __restrict__ bv) {
    int bm = blockIdx.x * 128;
    int tn = blockIdx.y;
    const float *B, *bias; float* C; int ldb, ldc, bn;
    if (tn < 8)       { B = wq; bias = bq; C = g_q; ldb = 1024; ldc = 1024; bn = tn * 128; }
    else if (tn < 10) { B = wk; bias = bk; C = g_k; ldb = 256;  ldc = 256;  bn = (tn - 8) * 128; }
    else              { B = wv; bias = bv; C = g_v; ldb = 256;  ldc = 256;  bn = (tn - 10) * 128; }
    float acc[8][8];
    const float* aRowPtr = g_h1 + (size_t)(bm + (threadIdx.x >> 1)) * D_;
    gemm_core(aRowPtr, B + bn, ldb, D_, acc);
    int tx = threadIdx.x & 15, ty = threadIdx.x >> 4;
    #pragma unroll
    for (int i = 0; i < 8; i++) {
        int r = bm + ty * 8 + i;
        #pragma unroll
        for (int j = 0; j < 8; j++) {
            int c = bn + tx * 8 + j;
            C[(size_t)r * ldc + c] = acc[i][j] + bias[c];
        }
    }
}

// ---------------- attention: one warp per (query, head) ----------------
__global__ void __launch_bounds__(256) attn_kernel(const float* __restrict__ sinkp) {
    int i = blockIdx.x;                 // query index
    int h = threadIdx.x >> 5;           // head 0..7
    int lane = threadIdx.x & 31;
    float sink = *sinkp;
    int kh = h >> 2;                    // GQA: kv head = h / 4
    const float4 qv = *(const float4*)&g_q[(size_t)i * D_ + h * HD_ + lane * 4];
    int jstart = i - (WS_ - 1); if (jstart < 0) jstart = 0;
    int nj = i - jstart + 1;
    const float scale = 0.08838834764831845f;  // 1/sqrt(128)
    float s0 = -1e30f, s1 = -1e30f;
    for (int jj = 0; jj < nj; ++jj) {
        int j = jstart + jj;
        float4 kv = *(const float4*)&g_k[(size_t)j * (NKV_ * HD_) + kh * HD_ + lane * 4];
        float p = qv.x * kv.x + qv.y * kv.y + qv.z * kv.z + qv.w * kv.w;
        #pragma unroll
        for (int off = 16; off; off >>= 1) p += __shfl_xor_sync(0xffffffffu, p, off);
        p *= scale;
        if (lane == (jj & 31)) { if (jj < 32) s0 = p; else s1 = p; }
    }
    float m = fmaxf(s0, s1);
    #pragma unroll
    for (int off = 16; off; off >>= 1) m = fmaxf(m, __shfl_xor_sync(0xffffffffu, m, off));
    m = fmaxf(m, sink);
    float e0 = expf(s0 - m), e1 = expf(s1 - m);
    float dsum = e0 + e1;
    #pragma unroll
    for (int off = 16; off; off >>= 1) dsum += __shfl_xor_sync(0xffffffffu, dsum, off);
    dsum += expf(sink - m);
    float4 acc = {0.f, 0.f, 0.f, 0.f};
    for (int jj = 0; jj < nj; ++jj) {
        int j = jstart + jj;
        float esel = (jj < 32) ? e0 : e1;
        float p = __shfl_sync(0xffffffffu, esel, jj & 31);
        float4 vv = *(const float4*)&g_v[(size_t)j * (NKV_ * HD_) + kh * HD_ + lane * 4];
        acc.x += p * vv.x; acc.y += p * vv.y; acc.z += p * vv.z; acc.w += p * vv.w;
    }
    float inv = 1.0f / dsum;
    acc.x *= inv; acc.y *= inv; acc.z *= inv; acc.w *= inv;
    *(float4*)&g_attn[(size_t)i * D_ + h * HD_ + lane * 4] = acc;
}

// ---------------- output projection + residual ----------------
__global__ void __launch_bounds__(256) wo_kernel(const float* __restrict__ woW, const float* __restrict__ bo,
                                                 const float* __restrict__ x) {
    int bm = blockIdx.x * 128;
    int bn = blockIdx.y * 128;
    float acc[8][8];
    const float* aRowPtr = g_attn + (size_t)(bm + (threadIdx.x >> 1)) * D_;
    gemm_core(aRowPtr, woW + bn, D_, D_, acc);
    int tx = threadIdx.x & 15, ty = threadIdx.x >> 4;
    #pragma unroll
    for (int i = 0; i < 8; i++) {
        int r = bm + ty * 8 + i;
        #pragma unroll
        for (int j = 0; j < 8; j++) {
            int c = bn + tx * 8 + j;
            g_x1[(size_t)r * D_ + c] = acc[i][j] + bo[c] + x[(size_t)r * D_ + c];
        }
    }
}

// ---------------- router: logits, top-2, gates, lists, prob colsums ----------------
__global__ void __launch_bounds__(128) router_kernel(const float* __restrict__ rw,
                                                     const float* __restrict__ rb) {
    int n = blockIdx.x;
    int tid = threadIdx.x;
    float acc[16];
    #pragma unroll
    for (int e = 0; e < 16; e++) acc[e] = 0.f;
    for (int d = tid; d < D_; d += 128) {
        float hv = g_h2[(size_t)n * D_ + d];
        const float4* r4 = (const float4*)(rw + (size_t)d * E_);
        float4 r0 = r4[0], r1 = r4[1], r2 = r4[2], r3 = r4[3];
        acc[0]  += hv * r0.x; acc[1]  += hv * r0.y; acc[2]  += hv * r0.z; acc[3]  += hv * r0.w;
        acc[4]  += hv * r1.x; acc[5]  += hv * r1.y; acc[6]  += hv * r1.z; acc[7]  += hv * r1.w;
        acc[8]  += hv * r2.x; acc[9]  += hv * r2.y; acc[10] += hv * r2.z; acc[11] += hv * r2.w;
        acc[12] += hv * r3.x; acc[13] += hv * r3.y; acc[14] += hv * r3.z; acc[15] += hv * r3.w;
    }
    #pragma unroll
    for (int e = 0; e < 16; e++) {
        #pragma unroll
        for (int off = 16; off; off >>= 1) acc[e] += __shfl_xor_sync(0xffffffffu, acc[e], off);
    }
    __shared__ float part[4][16];
    __shared__ float slog[16];
    int wid = tid >> 5, lane = tid & 31;
    if (lane == 0) {
        #pragma unroll
        for (int e = 0; e < 16; e++) part[wid][e] = acc[e];
    }
    __syncthreads();
    if (tid < 16) {
        float s = part[0][tid] + part[1][tid] + part[2][tid] + part[3][tid];
        slog[tid] = (s + rb[tid]) / 0.1f;
    }
    __syncthreads();
    if (tid == 0) {
        float l[16];
        float m = -1e30f;
        #pragma unroll
        for (int e = 0; e < 16; e++) { l[e] = slog[e]; m = fmaxf(m, l[e]); }
        float sum = 0.f;
        #pragma unroll
        for (int e = 0; e < 16; e++) sum += expf(l[e] - m);
        float invs = 1.0f / sum;
        #pragma unroll
        for (int e = 0; e < 16; e++) atomicAdd(&g_colsum[e], expf(l[e] - m) * invs);
        int i1 = 0;
        #pragma unroll
        for (int e = 1; e < 16; e++) if (l[e] > l[i1]) i1 = e;
        int i2 = (i1 == 0) ? 1 : 0;
        #pragma unroll
        for (int e = 0; e < 16; e++) if (e != i1 && l[e] > l[i2]) i2 = e;
        float e2 = expf(l[i2] - l[i1]);
        float wA = 1.0f / (1.0f + e2);
        float wB = e2 / (1.0f + e2);
        g_gate[n * 2 + 0] = wA;
        g_gate[n * 2 + 1] = wB;
        int p0 = atomicAdd(&g_cnt[i1], 1); g_list[i1 * S_ + p0] = n * 2 + 0;
        int p1 = atomicAdd(&g_cnt[i2], 1); g_list[i2 * S_ + p1] = n * 2 + 1;
    }
}

__global__ void aux_kernel(float* __restrict__ outp) {
    float v = (threadIdx.x < 16) ? g_colsum[threadIdx.x] : 0.f;
    v = v * v;
    #pragma unroll
    for (int off = 16; off; off >>= 1) v += __shfl_xor_sync(0xffffffffu, v, off);
    if (threadIdx.x == 0) outp[0] = v * (1.0f / (float)E_) * 1e-5f;
}

// ---------------- MoE GEMM 1: hmid = silu(X_gather @ w1[e] + b1[e]) ----------------
__global__ void __launch_bounds__(256) moe1_kernel(const float* __restrict__ w1,
                                                   const float* __restrict__ b1) {
    int e = blockIdx.z;
    int cnt = g_cnt[e];
    int bm = blockIdx.x * 128;
    if (bm >= cnt) return;
    int bn = blockIdx.y * 128;
    int ar = bm + (threadIdx.x >> 1);
    if (ar >= cnt) ar = cnt - 1;
    int pair = g_list[e * S_ + ar];
    const float* aRowPtr = g_h2 + (size_t)(pair >> 1) * D_;
    float acc[8][8];
    gemm_core(aRowPtr, w1 + (size_t)e * D_ * HDIM_ + bn, HDIM_, D_, acc);
    int tx = threadIdx.x & 15, ty = threadIdx.x >> 4;
    #pragma unroll
    for (int i = 0; i < 8; i++) {
        int r = bm + ty * 8 + i;
        if (r < cnt) {
            #pragma unroll
            for (int j = 0; j < 8; j++) {
                int c = bn + tx * 8 + j;
                float t = acc[i][j] + b1[e * HDIM_ + c];
                float s = t / (1.0f + expf(-t));   // silu
                g_hmid[(size_t)(e * S_ + r) * HDIM_ + c] = s;
            }
        }
    }
}

// ---------------- MoE GEMM 2: contrib[pair] = gate * (hmid @ w2[e] + b2[e]) ----------------
__global__ void __launch_bounds__(256) moe2_kernel(const float* __restrict__ w2,
                                                   const float* __restrict__ b2) {
    int e = blockIdx.z;
    int cnt = g_cnt[e];
    int bm = blockIdx.x * 128;
    if (bm >= cnt) return;
    int bn = blockIdx.y * 128;
    int ar = bm + (threadIdx.x >> 1);
    if (ar >= cnt) ar = cnt - 1;
    const float* aRowPtr = g_hmid + (size_t)(e * S_ + ar) * HDIM_;
    float acc[8][8];
    gemm_core(aRowPtr, w2 + (size_t)e * HDIM_ * D_ + bn, D_, HDIM_, acc);
    int tx = threadIdx.x & 15, ty = threadIdx.x >> 4;
    #pragma unroll
    for (int i = 0; i < 8; i++) {
        int r = bm + ty * 8 + i;
        if (r < cnt) {
            int pair = g_list[e * S_ + r];
            float g = g_gate[pair];
            #pragma unroll
            for (int j = 0; j < 8; j++) {
                int c = bn + tx * 8 + j;
                g_contrib[(size_t)pair * D_ + c] = g * (acc[i][j] + b2[e * D_ + c]);
            }
        }
    }
}

// ---------------- final combine: out = x1 + contrib[slot0] + contrib[slot1] ----------------
__global__ void __launch_bounds__(256) combine_kernel(float* __restrict__ out) {
    int n = blockIdx.x;
    int d = threadIdx.x * 4;
    float4 a = *(const float4*)&g_x1[(size_t)n * D_ + d];
    float4 b = *(const float4*)&g_contrib[(size_t)(n * 2 + 0) * D_ + d];
    float4 c = *(const float4*)&g_contrib[(size_t)(n * 2 + 1) * D_ + d];
    float4 r;
    r.x = a.x + b.x + c.x; r.y = a.y + b.y + c.y;
    r.z = a.z + b.z + c.z; r.w = a.w + b.w + c.w;
    *(float4*)&out[(size_t)n * D_ + d] = r;
}

// ---------------- host launcher ----------------
extern "C" void kernel_launch(void* const* d_in, const int* in_sizes, int n_in,
                              void* d_out, int out_size) {
    const float* x    = (const float*)d_in[0];
    const float* n1w  = (const float*)d_in[1];
    const float* wq   = (const float*)d_in[2];
    const float* bq   = (const float*)d_in[3];
    const float* wk   = (const float*)d_in[4];
    const float* bk   = (const float*)d_in[5];
    const float* wv   = (const float*)d_in[6];
    const float* bv   = (const float*)d_in[7];
    const float* woW  = (const float*)d_in[8];
    const float* bo   = (const float*)d_in[9];
    const float* sink = (const float*)d_in[10];
    const float* n2w  = (const float*)d_in[11];
    const float* rw   = (const float*)d_in[12];
    const float* rb   = (const float*)d_in[13];
    const float* w1   = (const float*)d_in[14];
    const float* b1   = (const float*)d_in[15];
    const float* w2   = (const float*)d_in[16];
    const float* b2   = (const float*)d_in[17];
    float* out = (float*)d_out;

    zero_kernel<<<1, 32>>>();
    rmsnorm1_kernel<<<S_, 256>>>(x, n1w);
    qkv_kernel<<<dim3(S_ / 128, 12), 256>>>(wq, bq, wk, bk, wv, bv);
    attn_kernel<<<S_, 256>>>(sink);
    wo_kernel<<<dim3(S_ / 128, D_ / 128), 256>>>(woW, bo, x);
    rmsnorm2_kernel<<<S_, 256>>>(n2w);
    router_kernel<<<S_, 128>>>(rw, rb);
    if (out_size > S_ * D_) {
        aux_kernel<<<1, 32>>>(out + (size_t)S_ * D_);
    }
    moe1_kernel<<<dim3(S_ / 128, HDIM_ / 128, E_), 256>>>(w1, b1);
    moe2_kernel<<<dim3(S_ / 128, D_ / 128, E_), 256>>>(w2, b2);
    combine_kernel<<<S_, 256>>>(out);
}

// round 7
// speedup vs baseline: 1.6799x; 1.6799x over previous
#include <cuda_runtime.h>
#include <cuda_bf16.h>
#include <math.h>

// Problem constants
#define S_   2048
#define D_   1024
#define NH_  8
#define NKV_ 2
#define HD_  128
#define WS_  64
#define E_   16
#define HDIM_ 512

// ---------------- scratch (device globals; no allocation allowed) ----------------
__device__ float g_h1[S_ * D_];            // rmsnorm1 output
__device__ float g_q[S_ * D_];
__device__ float g_k[S_ * NKV_ * HD_];
__device__ float g_v[S_ * NKV_ * HD_];
__device__ float g_attn[S_ * D_];
__device__ float g_x1[S_ * D_];
__device__ float g_h2[S_ * D_];
__device__ float g_hmid[E_ * S_ * HDIM_];
__device__ float g_contrib[S_ * 2 * D_];
__device__ float g_gate[S_ * 2];
__device__ int   g_list[E_ * S_];
__device__ int   g_cnt[E_];
__device__ float g_colsum[E_];

// ---------------- utility kernels ----------------
__global__ void zero_kernel() {
    int t = threadIdx.x;
    if (t < E_) { g_cnt[t] = 0; g_colsum[t] = 0.f; }
}

__device__ __forceinline__ void rms_row(const float* __restrict__ x,
                                        const float* __restrict__ w,
                                        float* __restrict__ o) {
    int n = blockIdx.x;
    int tid = threadIdx.x;            // 256 threads, 4 elems each
    float4 xv = *(const float4*)&x[n * D_ + tid * 4];
    float s = xv.x * xv.x + xv.y * xv.y + xv.z * xv.z + xv.w * xv.w;
    #pragma unroll
    for (int off = 16; off; off >>= 1) s += __shfl_xor_sync(0xffffffffu, s, off);
    __shared__ float part[8];
    __shared__ float inv;
    int wid = tid >> 5, lane = tid & 31;
    if (lane == 0) part[wid] = s;
    __syncthreads();
    if (tid == 0) {
        float t = 0.f;
        #pragma unroll
        for (int i = 0; i < 8; i++) t += part[i];
        inv = rsqrtf(t / (float)D_ + 1e-6f);
    }
    __syncthreads();
    float4 wv = *(const float4*)&w[tid * 4];
    float4 ov;
    ov.x = xv.x * inv * wv.x; ov.y = xv.y * inv * wv.y;
    ov.z = xv.z * inv * wv.z; ov.w = xv.w * inv * wv.w;
    *(float4*)&o[n * D_ + tid * 4] = ov;
}

__global__ void __launch_bounds__(256) rmsnorm1_kernel(const float* __restrict__ x,
                                                       const float* __restrict__ w) {
    rms_row(x, w, g_h1);
}
__global__ void __launch_bounds__(256) rmsnorm2_kernel(const float* __restrict__ w) {
    rms_row(g_x1, w, g_h2);
}

// ================= TF32x3 tensor-core GEMM core =================
// Block tile 128(M) x 64(N) x 16(K), 128 threads = 4 warps (2x2),
// warp tile 64x32 = 4(m16) x 4(n8) fragments, mma.m16n8k8 tf32, fp32 accum.
// 3xTF32: D += al*bh + ah*bl + ah*bh  (al*bl dropped, ~2^-22 rel).

#define BM 128
#define BN 64
#define BK 16
#define ASTR 136   // As row stride (floats): bank = qid*8+grp -> conflict-free
#define BSTR 72    // Bs row stride (floats): same property

__device__ __forceinline__ unsigned f2tf(float x) {
    unsigned u; asm("cvt.rna.tf32.f32 %0, %1;" : "=r"(u) : "f"(x)); return u;
}
__device__ __forceinline__ void split_tf(float x, unsigned& hi, unsigned& lo) {
    hi = f2tf(x);
    lo = f2tf(x - __uint_as_float(hi));
}
__device__ __forceinline__ void mma8(float* d, const unsigned* a, const unsigned* b) {
    asm volatile(
        "mma.sync.aligned.m16n8k8.row.col.f32.tf32.tf32.f32 "
        "{%0,%1,%2,%3}, {%4,%5,%6,%7}, {%8,%9}, {%0,%1,%2,%3};\n"
        : "+f"(d[0]), "+f"(d[1]), "+f"(d[2]), "+f"(d[3])
        : "r"(a[0]), "r"(a[1]), "r"(a[2]), "r"(a[3]), "r"(b[0]), "r"(b[1]));
}

// aRow: this thread's A row base (row bm+tid), contiguous K.
// bPtr: B + bn (row-major, leading dim ldb over K rows).
__device__ __forceinline__ void mma_gemm(const float* __restrict__ aRow,
                                         const float* __restrict__ bPtr,
                                         int ldb, int Kdim,
                                         float (&acc)[4][4][4]) {
    __shared__ float As[2][BK * ASTR];
    __shared__ float Bs[2][BK * BSTR];
    int tid = threadIdx.x;
    int lane = tid & 31;
    int wid = tid >> 5;
    int warpM = (wid >> 1) * 64;
    int warpN = (wid & 1) * 32;
    int grp = lane >> 2, qid = lane & 3;
    int bcol = (tid & 15) * 4;
    int bk0 = tid >> 4;                 // 0..7

    #pragma unroll
    for (int m = 0; m < 4; m++)
        #pragma unroll
        for (int n = 0; n < 4; n++)
            #pragma unroll
            for (int r = 0; r < 4; r++) acc[m][n][r] = 0.f;

    float4 ar[4]; float4 br[2];
    // prologue: load K-tile 0 into regs, stage into buffer 0
    #pragma unroll
    for (int i = 0; i < 4; i++) ar[i] = *(const float4*)(aRow + i * 4);
    br[0] = *(const float4*)(bPtr + (size_t)bk0 * ldb + bcol);
    br[1] = *(const float4*)(bPtr + (size_t)(bk0 + 8) * ldb + bcol);
    {
        float* as0 = As[0]; float* bs0 = Bs[0];
        #pragma unroll
        for (int i = 0; i < 4; i++) {
            as0[(i * 4 + 0) * ASTR + tid] = ar[i].x;
            as0[(i * 4 + 1) * ASTR + tid] = ar[i].y;
            as0[(i * 4 + 2) * ASTR + tid] = ar[i].z;
            as0[(i * 4 + 3) * ASTR + tid] = ar[i].w;
        }
        *(float4*)&bs0[bk0 * BSTR + bcol] = br[0];
        *(float4*)&bs0[(bk0 + 8) * BSTR + bcol] = br[1];
    }
    __syncthreads();

    int T = Kdim / BK;
    int buf = 0;
    for (int t = 0; t < T; ++t) {
        if (t + 1 < T) {   // prefetch next K-tile into registers
            int k0 = (t + 1) * BK;
            #pragma unroll
            for (int i = 0; i < 4; i++) ar[i] = *(const float4*)(aRow + k0 + i * 4);
            br[0] = *(const float4*)(bPtr + (size_t)(k0 + bk0) * ldb + bcol);
            br[1] = *(const float4*)(bPtr + (size_t)(k0 + bk0 + 8) * ldb + bcol);
        }
        const float* as = As[buf];
        const float* bs = Bs[buf];
        #pragma unroll
        for (int s = 0; s < 2; s++) {
            int ks = s * 8;
            unsigned ah[4][4], al[4][4];
            #pragma unroll
            for (int mf = 0; mf < 4; mf++) {
                int rb = warpM + mf * 16 + grp;
                split_tf(as[(ks + qid) * ASTR + rb],         ah[mf][0], al[mf][0]);
                split_tf(as[(ks + qid) * ASTR + rb + 8],     ah[mf][1], al[mf][1]);
                split_tf(as[(ks + qid + 4) * ASTR + rb],     ah[mf][2], al[mf][2]);
                split_tf(as[(ks + qid + 4) * ASTR + rb + 8], ah[mf][3], al[mf][3]);
            }
            #pragma unroll
            for (int nf = 0; nf < 4; nf++) {
                int nb = warpN + nf * 8 + grp;
                unsigned bh[2], bl[2];
                split_tf(bs[(ks + qid) * BSTR + nb],     bh[0], bl[0]);
                split_tf(bs[(ks + qid + 4) * BSTR + nb], bh[1], bl[1]);
                #pragma unroll
                for (int mf = 0; mf < 4; mf++) {
                    mma8(acc[mf][nf], al[mf], bh);
                    mma8(acc[mf][nf], ah[mf], bl);
                    mma8(acc[mf][nf], ah[mf], bh);
                }
            }
        }
        if (t + 1 < T) {   // stage prefetched tile into other buffer
            float* asw = As[buf ^ 1]; float* bsw = Bs[buf ^ 1];
            #pragma unroll
            for (int i = 0; i < 4; i++) {
                asw[(i * 4 + 0) * ASTR + tid] = ar[i].x;
                asw[(i * 4 + 1) * ASTR + tid] = ar[i].y;
                asw[(i * 4 + 2) * ASTR + tid] = ar[i].z;
                asw[(i * 4 + 3) * ASTR + tid] = ar[i].w;
            }
            *(float4*)&bsw[bk0 * BSTR + bcol] = br[0];
            *(float4*)&bsw[(bk0 + 8) * BSTR + bcol] = br[1];
        }
        __syncthreads();
        buf ^= 1;
    }
}

// ---------------- fused QKV GEMM: y tiles 0-15 Q, 16-19 K, 20-23 V ----------------
__global__ void __launch_bounds__(128) qkv_kernel(const float* __restrict__ wq, const float* __restrict__ bq,
                                                  const float* __restrict__ wk, const float* __restrict__ bk,
                                                  const float* __restrict__ wv, const float* __restrict__ bv) {
    int bm = blockIdx.x * BM;
    int tn = blockIdx.y;
    const float *B, *bias; float* C; int ldb, ldc, bn;
    if (tn < 16)      { B = wq; bias = bq; C = g_q; ldb = 1024; ldc = 1024; bn = tn * 64; }
    else if (tn < 20) { B = wk; bias = bk; C = g_k; ldb = 256;  ldc = 256;  bn = (tn - 16) * 64; }
    else              { B = wv; bias = bv; C = g_v; ldb = 256;  ldc = 256;  bn = (tn - 20) * 64; }
    float acc[4][4][4];
    const float* aRow = g_h1 + (size_t)(bm + threadIdx.x) * D_;
    mma_gemm(aRow, B + bn, ldb, D_, acc);
    int lane = threadIdx.x & 31, wid = threadIdx.x >> 5;
    int warpM = (wid >> 1) * 64, warpN = (wid & 1) * 32;
    int grp = lane >> 2, qid = lane & 3;
    #pragma unroll
    for (int mf = 0; mf < 4; mf++) {
        int r0 = bm + warpM + mf * 16 + grp;
        #pragma unroll
        for (int nf = 0; nf < 4; nf++) {
            int c0 = bn + warpN + nf * 8 + qid * 2;
            C[(size_t)r0 * ldc + c0]           = acc[mf][nf][0] + bias[c0];
            C[(size_t)r0 * ldc + c0 + 1]       = acc[mf][nf][1] + bias[c0 + 1];
            C[(size_t)(r0 + 8) * ldc + c0]     = acc[mf][nf][2] + bias[c0];
            C[(size_t)(r0 + 8) * ldc + c0 + 1] = acc[mf][nf][3] + bias[c0 + 1];
        }
    }
}

// ---------------- attention: one warp per (query, head) ----------------
__global__ void __launch_bounds__(256) attn_kernel(const float* __restrict__ sinkp) {
    int i = blockIdx.x;
    int h = threadIdx.x >> 5;
    int lane = threadIdx.x & 31;
    float sink = *sinkp;
    int kh = h >> 2;
    const float4 qv = *(const float4*)&g_q[(size_t)i * D_ + h * HD_ + lane * 4];
    int jstart = i - (WS_ - 1); if (jstart < 0) jstart = 0;
    int nj = i - jstart + 1;
    const float scale = 0.08838834764831845f;
    float s0 = -1e30f, s1 = -1e30f;
    for (int jj = 0; jj < nj; ++jj) {
        int j = jstart + jj;
        float4 kv = *(const float4*)&g_k[(size_t)j * (NKV_ * HD_) + kh * HD_ + lane * 4];
        float p = qv.x * kv.x + qv.y * kv.y + qv.z * kv.z + qv.w * kv.w;
        #pragma unroll
        for (int off = 16; off; off >>= 1) p += __shfl_xor_sync(0xffffffffu, p, off);
        p *= scale;
        if (lane == (jj & 31)) { if (jj < 32) s0 = p; else s1 = p; }
    }
    float m = fmaxf(s0, s1);
    #pragma unroll
    for (int off = 16; off; off >>= 1) m = fmaxf(m, __shfl_xor_sync(0xffffffffu, m, off));
    m = fmaxf(m, sink);
    float e0 = expf(s0 - m), e1 = expf(s1 - m);
    float dsum = e0 + e1;
    #pragma unroll
    for (int off = 16; off; off >>= 1) dsum += __shfl_xor_sync(0xffffffffu, dsum, off);
    dsum += expf(sink - m);
    float4 acc = {0.f, 0.f, 0.f, 0.f};
    for (int jj = 0; jj < nj; ++jj) {
        int j = jstart + jj;
        float esel = (jj < 32) ? e0 : e1;
        float p = __shfl_sync(0xffffffffu, esel, jj & 31);
        float4 vv = *(const float4*)&g_v[(size_t)j * (NKV_ * HD_) + kh * HD_ + lane * 4];
        acc.x += p * vv.x; acc.y += p * vv.y; acc.z += p * vv.z; acc.w += p * vv.w;
    }
    float inv = 1.0f / dsum;
    acc.x *= inv; acc.y *= inv; acc.z *= inv; acc.w *= inv;
    *(float4*)&g_attn[(size_t)i * D_ + h * HD_ + lane * 4] = acc;
}

// ---------------- output projection + residual ----------------
__global__ void __launch_bounds__(128) wo_kernel(const float* __restrict__ woW, const float* __restrict__ bo,
                                                 const float* __restrict__ x) {
    int bm = blockIdx.x * BM;
    int bn = blockIdx.y * BN;
    float acc[4][4][4];
    const float* aRow = g_attn + (size_t)(bm + threadIdx.x) * D_;
    mma_gemm(aRow, woW + bn, D_, D_, acc);
    int lane = threadIdx.x & 31, wid = threadIdx.x >> 5;
    int warpM = (wid >> 1) * 64, warpN = (wid & 1) * 32;
    int grp = lane >> 2, qid = lane & 3;
    #pragma unroll
    for (int mf = 0; mf < 4; mf++) {
        int r0 = bm + warpM + mf * 16 + grp;
        #pragma unroll
        for (int nf = 0; nf < 4; nf++) {
            int c0 = bn + warpN + nf * 8 + qid * 2;
            g_x1[(size_t)r0 * D_ + c0]           = acc[mf][nf][0] + bo[c0]     + x[(size_t)r0 * D_ + c0];
            g_x1[(size_t)r0 * D_ + c0 + 1]       = acc[mf][nf][1] + bo[c0 + 1] + x[(size_t)r0 * D_ + c0 + 1];
            g_x1[(size_t)(r0 + 8) * D_ + c0]     = acc[mf][nf][2] + bo[c0]     + x[(size_t)(r0 + 8) * D_ + c0];
            g_x1[(size_t)(r0 + 8) * D_ + c0 + 1] = acc[mf][nf][3] + bo[c0 + 1] + x[(size_t)(r0 + 8) * D_ + c0 + 1];
        }
    }
}

// ---------------- router ----------------
__global__ void __launch_bounds__(128) router_kernel(const float* __restrict__ rw,
                                                     const float* __restrict__ rb) {
    int n = blockIdx.x;
    int tid = threadIdx.x;
    float acc[16];
    #pragma unroll
    for (int e = 0; e < 16; e++) acc[e] = 0.f;
    for (int d = tid; d < D_; d += 128) {
        float hv = g_h2[(size_t)n * D_ + d];
        const float4* r4 = (const float4*)(rw + (size_t)d * E_);
        float4 r0 = r4[0], r1 = r4[1], r2 = r4[2], r3 = r4[3];
        acc[0]  += hv * r0.x; acc[1]  += hv * r0.y; acc[2]  += hv * r0.z; acc[3]  += hv * r0.w;
        acc[4]  += hv * r1.x; acc[5]  += hv * r1.y; acc[6]  += hv * r1.z; acc[7]  += hv * r1.w;
        acc[8]  += hv * r2.x; acc[9]  += hv * r2.y; acc[10] += hv * r2.z; acc[11] += hv * r2.w;
        acc[12] += hv * r3.x; acc[13] += hv * r3.y; acc[14] += hv * r3.z; acc[15] += hv * r3.w;
    }
    #pragma unroll
    for (int e = 0; e < 16; e++) {
        #pragma unroll
        for (int off = 16; off; off >>= 1) acc[e] += __shfl_xor_sync(0xffffffffu, acc[e], off);
    }
    __shared__ float part[4][16];
    __shared__ float slog[16];
    int wid = tid >> 5, lane = tid & 31;
    if (lane == 0) {
        #pragma unroll
        for (int e = 0; e < 16; e++) part[wid][e] = acc[e];
    }
    __syncthreads();
    if (tid < 16) {
        float s = part[0][tid] + part[1][tid] + part[2][tid] + part[3][tid];
        slog[tid] = (s + rb[tid]) / 0.1f;
    }
    __syncthreads();
    if (tid == 0) {
        float l[16];
        float m = -1e30f;
        #pragma unroll
        for (int e = 0; e < 16; e++) { l[e] = slog[e]; m = fmaxf(m, l[e]); }
        float sum = 0.f;
        #pragma unroll
        for (int e = 0; e < 16; e++) sum += expf(l[e] - m);
        float invs = 1.0f / sum;
        #pragma unroll
        for (int e = 0; e < 16; e++) atomicAdd(&g_colsum[e], expf(l[e] - m) * invs);
        int i1 = 0;
        #pragma unroll
        for (int e = 1; e < 16; e++) if (l[e] > l[i1]) i1 = e;
        int i2 = (i1 == 0) ? 1 : 0;
        #pragma unroll
        for (int e = 0; e < 16; e++) if (e != i1 && l[e] > l[i2]) i2 = e;
        float e2 = expf(l[i2] - l[i1]);
        g_gate[n * 2 + 0] = 1.0f / (1.0f + e2);
        g_gate[n * 2 + 1] = e2 / (1.0f + e2);
        int p0 = atomicAdd(&g_cnt[i1], 1); g_list[i1 * S_ + p0] = n * 2 + 0;
        int p1 = atomicAdd(&g_cnt[i2], 1); g_list[i2 * S_ + p1] = n * 2 + 1;
    }
}

__global__ void aux_kernel(float* __restrict__ outp) {
    float v = (threadIdx.x < 16) ? g_colsum[threadIdx.x] : 0.f;
    v = v * v;
    #pragma unroll
    for (int off = 16; off; off >>= 1) v += __shfl_xor_sync(0xffffffffu, v, off);
    if (threadIdx.x == 0) outp[0] = v * (1.0f / (float)E_) * 1e-5f;
}

// ---------------- MoE GEMM 1: hmid = silu(X_gather @ w1[e] + b1[e]) ----------------
__global__ void __launch_bounds__(128) moe1_kernel(const float* __restrict__ w1,
                                                   const float* __restrict__ b1) {
    int e = blockIdx.z;
    int cnt = g_cnt[e];
    int bm = blockIdx.x * BM;
    if (bm >= cnt) return;
    int bn = blockIdx.y * BN;
    int ar = bm + threadIdx.x;
    if (ar >= cnt) ar = cnt - 1;
    int pair = g_list[e * S_ + ar];
    const float* aRow = g_h2 + (size_t)(pair >> 1) * D_;
    float acc[4][4][4];
    mma_gemm(aRow, w1 + (size_t)e * D_ * HDIM_ + bn, HDIM_, D_, acc);
    int lane = threadIdx.x & 31, wid = threadIdx.x >> 5;
    int warpM = (wid >> 1) * 64, warpN = (wid & 1) * 32;
    int grp = lane >> 2, qid = lane & 3;
    #pragma unroll
    for (int mf = 0; mf < 4; mf++) {
        int r0 = bm + warpM + mf * 16 + grp;
        #pragma unroll
        for (int nf = 0; nf < 4; nf++) {
            int c0 = bn + warpN + nf * 8 + qid * 2;
            #pragma unroll
            for (int rr = 0; rr < 2; rr++) {
                int r = r0 + rr * 8;
                if (r < cnt) {
                    float t0 = acc[mf][nf][rr * 2 + 0] + b1[e * HDIM_ + c0];
                    float t1 = acc[mf][nf][rr * 2 + 1] + b1[e * HDIM_ + c0 + 1];
                    g_hmid[(size_t)(e * S_ + r) * HDIM_ + c0]     = t0 / (1.0f + expf(-t0));
                    g_hmid[(size_t)(e * S_ + r) * HDIM_ + c0 + 1] = t1 / (1.0f + expf(-t1));
                }
            }
        }
    }
}

// ---------------- MoE GEMM 2: contrib[pair] = gate * (hmid @ w2[e] + b2[e]) ----------------
__global__ void __launch_bounds__(128) moe2_kernel(const float* __restrict__ w2,
                                                   const float* __restrict__ b2) {
    int e = blockIdx.z;
    int cnt = g_cnt[e];
    int bm = blockIdx.x * BM;
    if (bm >= cnt) return;
    int bn = blockIdx.y * BN;
    int ar = bm + threadIdx.x;
    if (ar >= cnt) ar = cnt - 1;
    const float* aRow = g_hmid + (size_t)(e * S_ + ar) * HDIM_;
    float acc[4][4][4];
    mma_gemm(aRow, w2 + (size_t)e * HDIM_ * D_ + bn, D_, HDIM_, acc);
    int lane = threadIdx.x & 31, wid = threadIdx.x >> 5;
    int warpM = (wid >> 1) * 64, warpN = (wid & 1) * 32;
    int grp = lane >> 2, qid = lane & 3;
    #pragma unroll
    for (int mf = 0; mf < 4; mf++) {
        int r0 = bm + warpM + mf * 16 + grp;
        #pragma unroll
        for (int nf = 0; nf < 4; nf++) {
            int c0 = bn + warpN + nf * 8 + qid * 2;
            #pragma unroll
            for (int rr = 0; rr < 2; rr++) {
                int r = r0 + rr * 8;
                if (r < cnt) {
                    int pair = g_list[e * S_ + r];
                    float g = g_gate[pair];
                    g_contrib[(size_t)pair * D_ + c0]     = g * (acc[mf][nf][rr * 2 + 0] + b2[e * D_ + c0]);
                    g_contrib[(size_t)pair * D_ + c0 + 1] = g * (acc[mf][nf][rr * 2 + 1] + b2[e * D_ + c0 + 1]);
                }
            }
        }
    }
}

// ---------------- final combine ----------------
__global__ void __launch_bounds__(256) combine_kernel(float* __restrict__ out) {
    int n = blockIdx.x;
    int d = threadIdx.x * 4;
    float4 a = *(const float4*)&g_x1[(size_t)n * D_ + d];
    float4 b = *(const float4*)&g_contrib[(size_t)(n * 2 + 0) * D_ + d];
    float4 c = *(const float4*)&g_contrib[(size_t)(n * 2 + 1) * D_ + d];
    float4 r;
    r.x = a.x + b.x + c.x; r.y = a.y + b.y + c.y;
    r.z = a.z + b.z + c.z; r.w = a.w + b.w + c.w;
    *(float4*)&out[(size_t)n * D_ + d] = r;
}

// ---------------- host launcher ----------------
extern "C" void kernel_launch(void* const* d_in, const int* in_sizes, int n_in,
                              void* d_out, int out_size) {
    const float* x    = (const float*)d_in[0];
    const float* n1w  = (const float*)d_in[1];
    const float* wq   = (const float*)d_in[2];
    const float* bq   = (const float*)d_in[3];
    const float* wk   = (const float*)d_in[4];
    const float* bk   = (const float*)d_in[5];
    const float* wv   = (const float*)d_in[6];
    const float* bv   = (const float*)d_in[7];
    const float* woW  = (const float*)d_in[8];
    const float* bo   = (const float*)d_in[9];
    const float* sink = (const float*)d_in[10];
    const float* n2w  = (const float*)d_in[11];
    const float* rw   = (const float*)d_in[12];
    const float* rb   = (const float*)d_in[13];
    const float* w1   = (const float*)d_in[14];
    const float* b1   = (const float*)d_in[15];
    const float* w2   = (const float*)d_in[16];
    const float* b2   = (const float*)d_in[17];
    float* out = (float*)d_out;

    zero_kernel<<<1, 32>>>();
    rmsnorm1_kernel<<<S_, 256>>>(x, n1w);
    qkv_kernel<<<dim3(S_ / BM, 24), 128>>>(wq, bq, wk, bk, wv, bv);
    attn_kernel<<<S_, 256>>>(sink);
    wo_kernel<<<dim3(S_ / BM, D_ / BN), 128>>>(woW, bo, x);
    rmsnorm2_kernel<<<S_, 256>>>(n2w);
    router_kernel<<<S_, 128>>>(rw, rb);
    if (out_size > S_ * D_) {
        aux_kernel<<<1, 32>>>(out + (size_t)S_ * D_);
    }
    moe1_kernel<<<dim3(S_ / BM, HDIM_ / BN, E_), 128>>>(w1, b1);
    moe2_kernel<<<dim3(S_ / BM, D_ / BN, E_), 128>>>(w2, b2);
    combine_kernel<<<S_, 256>>>(out);
}